// round 4
// baseline (speedup 1.0000x reference)
#include <cuda_runtime.h>
#include <math.h>

#define EMB   1024
#define NH    16
#define HD    64
#define INNER 1024
#define BATCH 2
#define SEQ   2048
#define MROWS (BATCH*SEQ)   // 4096

// Scratch (allocation-free rule: device globals)
__device__ float g_q[(size_t)MROWS*INNER];
__device__ float g_k[(size_t)MROWS*INNER];
__device__ float g_v[(size_t)MROWS*INNER];
__device__ float g_att[(size_t)MROWS*INNER];

// ---------------------------------------------------------------------------
// SGEMM: C[m][n] = sum_k A[m][k] * W[n][k]  (+ bias[n])
// Both operands row-major, K contiguous (X @ W^T with torch Linear layout).
// 128x128 tile, BK=8, 256 threads, 8x8 microtile. M%128==0, N%128==0, K%8==0.
// ---------------------------------------------------------------------------
template<bool BIAS>
__global__ __launch_bounds__(256) void sgemm_nt(
    const float* __restrict__ A, const float* __restrict__ W,
    const float* __restrict__ bias, float* __restrict__ C,
    int M, int N, int K)
{
    __shared__ float As[8][132];
    __shared__ float Bs[8][132];

    const int bm = blockIdx.y * 128;
    const int bn = blockIdx.x * 128;
    const int tid = threadIdx.x;
    const int tx = tid & 15;        // 0..15  -> 8 cols each
    const int ty = tid >> 4;        // 0..15  -> 8 rows each
    const int lr = tid >> 1;        // 0..127 tile row for loads
    const int lc = (tid & 1) * 4;   // 0 or 4 (float4 col within BK=8)

    float acc[8][8];
    #pragma unroll
    for (int i = 0; i < 8; i++)
        #pragma unroll
        for (int j = 0; j < 8; j++) acc[i][j] = 0.f;

    const float* Arow = A + (size_t)(bm + lr) * K + lc;
    const float* Wrow = W + (size_t)(bn + lr) * K + lc;

    for (int k0 = 0; k0 < K; k0 += 8) {
        float4 a = *(const float4*)(Arow + k0);
        float4 b = *(const float4*)(Wrow + k0);
        As[lc+0][lr] = a.x; As[lc+1][lr] = a.y; As[lc+2][lr] = a.z; As[lc+3][lr] = a.w;
        Bs[lc+0][lr] = b.x; Bs[lc+1][lr] = b.y; Bs[lc+2][lr] = b.z; Bs[lc+3][lr] = b.w;
        __syncthreads();

        #pragma unroll
        for (int k = 0; k < 8; ++k) {
            float4 a0 = *(const float4*)&As[k][ty*8];
            float4 a1 = *(const float4*)&As[k][ty*8 + 4];
            float4 b0 = *(const float4*)&Bs[k][tx*8];
            float4 b1 = *(const float4*)&Bs[k][tx*8 + 4];
            float ra[8] = {a0.x,a0.y,a0.z,a0.w,a1.x,a1.y,a1.z,a1.w};
            float rb[8] = {b0.x,b0.y,b0.z,b0.w,b1.x,b1.y,b1.z,b1.w};
            #pragma unroll
            for (int i = 0; i < 8; i++)
                #pragma unroll
                for (int j = 0; j < 8; j++)
                    acc[i][j] += ra[i] * rb[j];
        }
        __syncthreads();
    }

    float bb[8] = {0,0,0,0,0,0,0,0};
    if (BIAS) {
        float4 b0 = *(const float4*)&bias[bn + tx*8];
        float4 b1 = *(const float4*)&bias[bn + tx*8 + 4];
        bb[0]=b0.x; bb[1]=b0.y; bb[2]=b0.z; bb[3]=b0.w;
        bb[4]=b1.x; bb[5]=b1.y; bb[6]=b1.z; bb[7]=b1.w;
    }

    #pragma unroll
    for (int i = 0; i < 8; i++) {
        float* crow = C + (size_t)(bm + ty*8 + i) * N + bn + tx*8;
        float4 o0 = make_float4(acc[i][0]+bb[0], acc[i][1]+bb[1], acc[i][2]+bb[2], acc[i][3]+bb[3]);
        float4 o1 = make_float4(acc[i][4]+bb[4], acc[i][5]+bb[5], acc[i][6]+bb[6], acc[i][7]+bb[7]);
        *(float4*)(crow)     = o0;
        *(float4*)(crow + 4) = o1;
    }
}

// ---------------------------------------------------------------------------
// Flash-style causal attention over projected Q/K/V stored as [B,S,H,D].
// 1 thread = 1 query row. 128 queries / block, one (b,h) per block.z/y.
// K/V tiles of 32 keys in smem, read via float4 warp-broadcast.
// positional_mask is int32 (harness converts bool -> int32).
// ---------------------------------------------------------------------------
__global__ __launch_bounds__(128) void attn_kernel(
    const float* __restrict__ Q, const float* __restrict__ K,
    const float* __restrict__ V, const int* __restrict__ pmask,
    const int* __restrict__ fmask, float* __restrict__ O)
{
    const int b  = blockIdx.z;
    const int h  = blockIdx.y;
    const int q0 = blockIdx.x * 128;
    const int qi = q0 + threadIdx.x;

    __shared__ float ks[32][64];
    __shared__ float vs[32][64];

    const float scale = 0.125f;  // 1/sqrt(64)
    float qreg[64];
    {
        const float* qptr = Q + (size_t)(b*SEQ + qi) * INNER + h*HD;
        #pragma unroll
        for (int i = 0; i < 16; i++) {
            float4 t = *(const float4*)(qptr + i*4);
            qreg[i*4+0] = t.x * scale; qreg[i*4+1] = t.y * scale;
            qreg[i*4+2] = t.z * scale; qreg[i*4+3] = t.w * scale;
        }
    }

    float acc[64];
    #pragma unroll
    for (int d = 0; d < 64; d++) acc[d] = 0.f;
    float m = -INFINITY, l = 0.f;

    const bool causal = (*fmask != 0);
    const int jmax = causal ? (q0 + 127) : (SEQ - 1);
    const int* pm = pmask + (size_t)b * SEQ;

    const float* kbase0 = K + (size_t)(b*SEQ) * INNER + h*HD;
    const float* vbase0 = V + (size_t)(b*SEQ) * INNER + h*HD;

    for (int j0 = 0; j0 <= jmax; j0 += 32) {
        // load 32x64 K and V tiles, 4 float4 per thread each
        {
            const int t = threadIdx.x;
            #pragma unroll
            for (int i = 0; i < 4; i++) {
                int idx4 = t + i*128;            // 0..511
                int row  = idx4 >> 4;            // 0..31
                int c4   = (idx4 & 15) * 4;      // 0..60
                const float* kp = kbase0 + (size_t)(j0 + row) * INNER + c4;
                const float* vp = vbase0 + (size_t)(j0 + row) * INNER + c4;
                *(float4*)&ks[row][c4] = *(const float4*)kp;
                *(float4*)&vs[row][c4] = *(const float4*)vp;
            }
        }
        __syncthreads();

        float s[32];
        #pragma unroll
        for (int jj = 0; jj < 32; jj++) {
            float sum = 0.f;
            #pragma unroll
            for (int d4 = 0; d4 < 16; d4++) {
                float4 kv = *(const float4*)&ks[jj][d4*4];
                sum += qreg[d4*4+0]*kv.x; sum += qreg[d4*4+1]*kv.y;
                sum += qreg[d4*4+2]*kv.z; sum += qreg[d4*4+3]*kv.w;
            }
            const int j = j0 + jj;
            const bool ok = (!causal || j <= qi) && (pm[j] != 0);
            s[jj] = ok ? sum : -INFINITY;
        }

        float tmax = s[0];
        #pragma unroll
        for (int jj = 1; jj < 32; jj++) tmax = fmaxf(tmax, s[jj]);

        const float m_new = fmaxf(m, tmax);
        if (m_new > -INFINITY) {
            const float corr = __expf(m - m_new);  // exp(-inf)=0 handles first tile
            l *= corr;
            #pragma unroll
            for (int d = 0; d < 64; d++) acc[d] *= corr;
            #pragma unroll
            for (int jj = 0; jj < 32; jj++) {
                const float p = __expf(s[jj] - m_new);
                l += p;
                #pragma unroll
                for (int d4 = 0; d4 < 16; d4++) {
                    float4 vv = *(const float4*)&vs[jj][d4*4];
                    acc[d4*4+0] += p * vv.x; acc[d4*4+1] += p * vv.y;
                    acc[d4*4+2] += p * vv.z; acc[d4*4+3] += p * vv.w;
                }
            }
            m = m_new;
        }
        __syncthreads();
    }

    const float inv = 1.f / l;
    float* optr = O + (size_t)(b*SEQ + qi) * INNER + h*HD;
    #pragma unroll
    for (int d4 = 0; d4 < 16; d4++) {
        float4 o = make_float4(acc[d4*4+0]*inv, acc[d4*4+1]*inv,
                               acc[d4*4+2]*inv, acc[d4*4+3]*inv);
        *(float4*)(optr + d4*4) = o;
    }
}

// ---------------------------------------------------------------------------
extern "C" void kernel_launch(void* const* d_in, const int* in_sizes, int n_in,
                              void* d_out, int out_size)
{
    const float* query = (const float*)d_in[0];
    const float* key   = (const float*)d_in[1];
    const float* value = (const float*)d_in[2];
    const int*   pmask = (const int*)d_in[3];
    const int*   fmask = (const int*)d_in[4];
    const float* Wq = (const float*)d_in[5];
    const float* Wk = (const float*)d_in[6];
    const float* Wv = (const float*)d_in[7];
    const float* Wo = (const float*)d_in[8];
    const float* bo = (const float*)d_in[9];
    float* out = (float*)d_out;

    float *gq, *gk, *gv, *gatt;
    cudaGetSymbolAddress((void**)&gq,   g_q);
    cudaGetSymbolAddress((void**)&gk,   g_k);
    cudaGetSymbolAddress((void**)&gv,   g_v);
    cudaGetSymbolAddress((void**)&gatt, g_att);

    dim3 ggrid(INNER/128, MROWS/128);   // (8, 32)
    sgemm_nt<false><<<ggrid, 256>>>(query, Wq, nullptr, gq, MROWS, INNER, EMB);
    sgemm_nt<false><<<ggrid, 256>>>(key,   Wk, nullptr, gk, MROWS, INNER, EMB);
    sgemm_nt<false><<<ggrid, 256>>>(value, Wv, nullptr, gv, MROWS, INNER, EMB);

    dim3 agrid(SEQ/128, NH, BATCH);     // (16, 16, 2)
    attn_kernel<<<agrid, 128>>>(gq, gk, gv, pmask, fmask, gatt);

    dim3 ogrid(EMB/128, MROWS/128);     // (8, 32)
    sgemm_nt<true><<<ogrid, 256>>>(gatt, Wo, bo, out, MROWS, EMB, INNER);
}

// round 9
// speedup vs baseline: 1.4110x; 1.4110x over previous
#include <cuda_runtime.h>
#include <cstdint>
#include <math.h>

#define EMB   1024
#define NH    16
#define HD    64
#define INNER 1024
#define BATCH 2
#define SEQ   2048
#define MROWS (BATCH*SEQ)   // 4096

// Scratch (allocation-free rule: device globals)
__device__ float g_q[(size_t)MROWS*INNER];
__device__ float g_k[(size_t)MROWS*INNER];
__device__ float g_v[(size_t)MROWS*INNER];
__device__ float g_att[(size_t)MROWS*INNER];

__device__ __forceinline__ uint32_t f2tf32(float x) {
    uint32_t r;
    asm("cvt.rna.tf32.f32 %0, %1;" : "=r"(r) : "f"(x));
    return r;
}

// ---------------------------------------------------------------------------
// TF32 mma.sync GEMM: C[m][n] = sum_k A[m][k]*W[n][k] (+bias[n])
// A:[M,1024] row-major, W:[N,1024] row-major (= B col-major for mma.row.col).
// CTA 128x128, K-chunk 32. 8 warps (4 m x 2 n), warp tile 32x64.
// mma.sync.aligned.m16n8k8.row.col.f32.tf32.tf32.f32
// Smem rows padded to 36 words -> conflict-free fragment LDS.
// ---------------------------------------------------------------------------
#define SPITCH 36

template<bool BIAS>
__global__ __launch_bounds__(256) void gemm_tf32(
    const float* __restrict__ A, const float* __restrict__ W,
    const float* __restrict__ bias, float* __restrict__ C)
{
    extern __shared__ uint32_t sm[];
    uint32_t* As = sm;                       // 128 * 36
    uint32_t* Bs = sm + 128 * SPITCH;        // 128 * 36

    const int tid  = threadIdx.x;
    const int wid  = tid >> 5;
    const int lane = tid & 31;
    const int g    = lane >> 2;      // 0..7
    const int t4   = lane & 3;       // 0..3
    const int wm   = (wid & 3) * 32; // warp m offset
    const int wn   = (wid >> 2) * 64;// warp n offset

    const int bm = blockIdx.y * 128;
    const int bn = blockIdx.x * 128;
    const int K  = 1024;

    // load indexing: 4 float4 each for A and B per thread per chunk
    const int lrow = tid >> 3;          // base row 0..31 (x4 iters -> 128)
    const int lc4  = tid & 7;           // float4 index within 32-float row

    float c[2][8][4];
    #pragma unroll
    for (int mt = 0; mt < 2; mt++)
        #pragma unroll
        for (int nt = 0; nt < 8; nt++)
            #pragma unroll
            for (int i = 0; i < 4; i++) c[mt][nt][i] = 0.f;

    for (int ch = 0; ch < 32; ch++) {
        const int k0 = ch * 32;
        // stage gmem loads in regs (overlap with previous chunk's mma)
        float4 av[4], bv[4];
        #pragma unroll
        for (int i = 0; i < 4; i++) {
            int row = lrow + i * 32;
            av[i] = *(const float4*)(A + (size_t)(bm + row) * K + k0 + lc4 * 4);
            bv[i] = *(const float4*)(W + (size_t)(bn + row) * K + k0 + lc4 * 4);
        }
        __syncthreads();
        #pragma unroll
        for (int i = 0; i < 4; i++) {
            int row = lrow + i * 32;
            uint32_t* ap = As + row * SPITCH + lc4 * 4;
            uint32_t* bp = Bs + row * SPITCH + lc4 * 4;
            ap[0] = f2tf32(av[i].x); ap[1] = f2tf32(av[i].y);
            ap[2] = f2tf32(av[i].z); ap[3] = f2tf32(av[i].w);
            bp[0] = f2tf32(bv[i].x); bp[1] = f2tf32(bv[i].y);
            bp[2] = f2tf32(bv[i].z); bp[3] = f2tf32(bv[i].w);
        }
        __syncthreads();

        #pragma unroll
        for (int kk = 0; kk < 32; kk += 8) {
            uint32_t a[2][4];
            #pragma unroll
            for (int mt = 0; mt < 2; mt++) {
                const uint32_t* base = As + (wm + mt * 16 + g) * SPITCH + kk + t4;
                a[mt][0] = base[0];
                a[mt][1] = base[8 * SPITCH];
                a[mt][2] = base[4];
                a[mt][3] = base[8 * SPITCH + 4];
            }
            #pragma unroll
            for (int nt = 0; nt < 8; nt++) {
                const uint32_t* bb = Bs + (wn + nt * 8 + g) * SPITCH + kk + t4;
                uint32_t b0 = bb[0];
                uint32_t b1 = bb[4];
                #pragma unroll
                for (int mt = 0; mt < 2; mt++) {
                    asm volatile(
                        "mma.sync.aligned.m16n8k8.row.col.f32.tf32.tf32.f32 "
                        "{%0,%1,%2,%3}, {%4,%5,%6,%7}, {%8,%9}, {%0,%1,%2,%3};"
                        : "+f"(c[mt][nt][0]), "+f"(c[mt][nt][1]),
                          "+f"(c[mt][nt][2]), "+f"(c[mt][nt][3])
                        : "r"(a[mt][0]), "r"(a[mt][1]), "r"(a[mt][2]), "r"(a[mt][3]),
                          "r"(b0), "r"(b1));
                }
            }
        }
    }

    // epilogue: c0,c1 -> (row g, cols 2t4, 2t4+1), c2,c3 -> row g+8
    #pragma unroll
    for (int mt = 0; mt < 2; mt++) {
        #pragma unroll
        for (int nt = 0; nt < 8; nt++) {
            const int col = bn + wn + nt * 8 + 2 * t4;
            float bx = 0.f, by = 0.f;
            if (BIAS) { bx = bias[col]; by = bias[col + 1]; }
            const int r0 = bm + wm + mt * 16 + g;
            float2 v0 = make_float2(c[mt][nt][0] + bx, c[mt][nt][1] + by);
            float2 v1 = make_float2(c[mt][nt][2] + bx, c[mt][nt][3] + by);
            *(float2*)(C + (size_t)r0 * 1024 + col)       = v0;
            *(float2*)(C + (size_t)(r0 + 8) * 1024 + col) = v1;
        }
    }
}

// ---------------------------------------------------------------------------
// Flash-style causal attention (unchanged from R4 passing version).
// ---------------------------------------------------------------------------
__global__ __launch_bounds__(128) void attn_kernel(
    const float* __restrict__ Q, const float* __restrict__ K,
    const float* __restrict__ V, const int* __restrict__ pmask,
    const int* __restrict__ fmask, float* __restrict__ O)
{
    const int b  = blockIdx.z;
    const int h  = blockIdx.y;
    const int q0 = blockIdx.x * 128;
    const int qi = q0 + threadIdx.x;

    __shared__ float ks[32][64];
    __shared__ float vs[32][64];

    const float scale = 0.125f;  // 1/sqrt(64)
    float qreg[64];
    {
        const float* qptr = Q + (size_t)(b*SEQ + qi) * INNER + h*HD;
        #pragma unroll
        for (int i = 0; i < 16; i++) {
            float4 t = *(const float4*)(qptr + i*4);
            qreg[i*4+0] = t.x * scale; qreg[i*4+1] = t.y * scale;
            qreg[i*4+2] = t.z * scale; qreg[i*4+3] = t.w * scale;
        }
    }

    float acc[64];
    #pragma unroll
    for (int d = 0; d < 64; d++) acc[d] = 0.f;
    float m = -INFINITY, l = 0.f;

    const bool causal = (*fmask != 0);
    const int jmax = causal ? (q0 + 127) : (SEQ - 1);
    const int* pm = pmask + (size_t)b * SEQ;

    const float* kbase0 = K + (size_t)(b*SEQ) * INNER + h*HD;
    const float* vbase0 = V + (size_t)(b*SEQ) * INNER + h*HD;

    for (int j0 = 0; j0 <= jmax; j0 += 32) {
        {
            const int t = threadIdx.x;
            #pragma unroll
            for (int i = 0; i < 4; i++) {
                int idx4 = t + i*128;            // 0..511
                int row  = idx4 >> 4;            // 0..31
                int c4   = (idx4 & 15) * 4;      // 0..60
                const float* kp = kbase0 + (size_t)(j0 + row) * INNER + c4;
                const float* vp = vbase0 + (size_t)(j0 + row) * INNER + c4;
                *(float4*)&ks[row][c4] = *(const float4*)kp;
                *(float4*)&vs[row][c4] = *(const float4*)vp;
            }
        }
        __syncthreads();

        float s[32];
        #pragma unroll
        for (int jj = 0; jj < 32; jj++) {
            float sum = 0.f;
            #pragma unroll
            for (int d4 = 0; d4 < 16; d4++) {
                float4 kv = *(const float4*)&ks[jj][d4*4];
                sum += qreg[d4*4+0]*kv.x; sum += qreg[d4*4+1]*kv.y;
                sum += qreg[d4*4+2]*kv.z; sum += qreg[d4*4+3]*kv.w;
            }
            const int j = j0 + jj;
            const bool ok = (!causal || j <= qi) && (pm[j] != 0);
            s[jj] = ok ? sum : -INFINITY;
        }

        float tmax = s[0];
        #pragma unroll
        for (int jj = 1; jj < 32; jj++) tmax = fmaxf(tmax, s[jj]);

        const float m_new = fmaxf(m, tmax);
        if (m_new > -INFINITY) {
            const float corr = __expf(m - m_new);
            l *= corr;
            #pragma unroll
            for (int d = 0; d < 64; d++) acc[d] *= corr;
            #pragma unroll
            for (int jj = 0; jj < 32; jj++) {
                const float p = __expf(s[jj] - m_new);
                l += p;
                #pragma unroll
                for (int d4 = 0; d4 < 16; d4++) {
                    float4 vv = *(const float4*)&vs[jj][d4*4];
                    acc[d4*4+0] += p * vv.x; acc[d4*4+1] += p * vv.y;
                    acc[d4*4+2] += p * vv.z; acc[d4*4+3] += p * vv.w;
                }
            }
            m = m_new;
        }
        __syncthreads();
    }

    const float inv = 1.f / l;
    float* optr = O + (size_t)(b*SEQ + qi) * INNER + h*HD;
    #pragma unroll
    for (int d4 = 0; d4 < 16; d4++) {
        float4 o = make_float4(acc[d4*4+0]*inv, acc[d4*4+1]*inv,
                               acc[d4*4+2]*inv, acc[d4*4+3]*inv);
        *(float4*)(optr + d4*4) = o;
    }
}

// ---------------------------------------------------------------------------
extern "C" void kernel_launch(void* const* d_in, const int* in_sizes, int n_in,
                              void* d_out, int out_size)
{
    const float* query = (const float*)d_in[0];
    const float* key   = (const float*)d_in[1];
    const float* value = (const float*)d_in[2];
    const int*   pmask = (const int*)d_in[3];
    const int*   fmask = (const int*)d_in[4];
    const float* Wq = (const float*)d_in[5];
    const float* Wk = (const float*)d_in[6];
    const float* Wv = (const float*)d_in[7];
    const float* Wo = (const float*)d_in[8];
    const float* bo = (const float*)d_in[9];
    float* out = (float*)d_out;

    float *gq, *gk, *gv, *gatt;
    cudaGetSymbolAddress((void**)&gq,   g_q);
    cudaGetSymbolAddress((void**)&gk,   g_k);
    cudaGetSymbolAddress((void**)&gv,   g_v);
    cudaGetSymbolAddress((void**)&gatt, g_att);

    const int SMEM_BYTES = 2 * 128 * SPITCH * 4;   // 36864
    cudaFuncSetAttribute(gemm_tf32<false>,
                         cudaFuncAttributeMaxDynamicSharedMemorySize, SMEM_BYTES);
    cudaFuncSetAttribute(gemm_tf32<true>,
                         cudaFuncAttributeMaxDynamicSharedMemorySize, SMEM_BYTES);

    dim3 ggrid(INNER/128, MROWS/128);   // (8, 32)
    gemm_tf32<false><<<ggrid, 256, SMEM_BYTES>>>(query, Wq, nullptr, gq);
    gemm_tf32<false><<<ggrid, 256, SMEM_BYTES>>>(key,   Wk, nullptr, gk);
    gemm_tf32<false><<<ggrid, 256, SMEM_BYTES>>>(value, Wv, nullptr, gv);

    dim3 agrid(SEQ/128, NH, BATCH);     // (16, 16, 2)
    attn_kernel<<<agrid, 128>>>(gq, gk, gv, pmask, fmask, gatt);

    dim3 ogrid(EMB/128, MROWS/128);     // (8, 32)
    gemm_tf32<true><<<ogrid, 256, SMEM_BYTES>>>(gatt, Wo, bo, out);
}

// round 11
// speedup vs baseline: 3.6031x; 2.5536x over previous
#include <cuda_runtime.h>
#include <cstdint>
#include <math.h>

#define EMB   1024
#define NH    16
#define HD    64
#define INNER 1024
#define BATCH 2
#define SEQ   2048
#define MROWS (BATCH*SEQ)   // 4096

// Scratch (allocation-free rule: device globals)
__device__ float g_q[(size_t)MROWS*INNER];
__device__ float g_k[(size_t)MROWS*INNER];
__device__ float g_v[(size_t)MROWS*INNER];
__device__ float g_att[(size_t)MROWS*INNER];

__device__ __forceinline__ uint32_t f2tf32(float x) {
    uint32_t r;
    asm("cvt.rna.tf32.f32 %0, %1;" : "=r"(r) : "f"(x));
    return r;
}

#define MMA_TF32(c, a0,a1,a2,a3, b0,b1)                                        \
    asm volatile(                                                              \
        "mma.sync.aligned.m16n8k8.row.col.f32.tf32.tf32.f32 "                  \
        "{%0,%1,%2,%3}, {%4,%5,%6,%7}, {%8,%9}, {%0,%1,%2,%3};"                \
        : "+f"((c)[0]), "+f"((c)[1]), "+f"((c)[2]), "+f"((c)[3])               \
        : "r"(a0), "r"(a1), "r"(a2), "r"(a3), "r"(b0), "r"(b1))

// ---------------------------------------------------------------------------
// TF32 mma.sync GEMM (unchanged from R9 passing version)
// ---------------------------------------------------------------------------
#define SPITCH 36

template<bool BIAS>
__global__ __launch_bounds__(256) void gemm_tf32(
    const float* __restrict__ A, const float* __restrict__ W,
    const float* __restrict__ bias, float* __restrict__ C)
{
    extern __shared__ uint32_t sm[];
    uint32_t* As = sm;                       // 128 * 36
    uint32_t* Bs = sm + 128 * SPITCH;        // 128 * 36

    const int tid  = threadIdx.x;
    const int wid  = tid >> 5;
    const int lane = tid & 31;
    const int g    = lane >> 2;      // 0..7
    const int t4   = lane & 3;       // 0..3
    const int wm   = (wid & 3) * 32; // warp m offset
    const int wn   = (wid >> 2) * 64;// warp n offset

    const int bm = blockIdx.y * 128;
    const int bn = blockIdx.x * 128;
    const int K  = 1024;

    const int lrow = tid >> 3;
    const int lc4  = tid & 7;

    float c[2][8][4];
    #pragma unroll
    for (int mt = 0; mt < 2; mt++)
        #pragma unroll
        for (int nt = 0; nt < 8; nt++)
            #pragma unroll
            for (int i = 0; i < 4; i++) c[mt][nt][i] = 0.f;

    for (int ch = 0; ch < 32; ch++) {
        const int k0 = ch * 32;
        float4 av[4], bv[4];
        #pragma unroll
        for (int i = 0; i < 4; i++) {
            int row = lrow + i * 32;
            av[i] = *(const float4*)(A + (size_t)(bm + row) * K + k0 + lc4 * 4);
            bv[i] = *(const float4*)(W + (size_t)(bn + row) * K + k0 + lc4 * 4);
        }
        __syncthreads();
        #pragma unroll
        for (int i = 0; i < 4; i++) {
            int row = lrow + i * 32;
            uint32_t* ap = As + row * SPITCH + lc4 * 4;
            uint32_t* bp = Bs + row * SPITCH + lc4 * 4;
            ap[0] = f2tf32(av[i].x); ap[1] = f2tf32(av[i].y);
            ap[2] = f2tf32(av[i].z); ap[3] = f2tf32(av[i].w);
            bp[0] = f2tf32(bv[i].x); bp[1] = f2tf32(bv[i].y);
            bp[2] = f2tf32(bv[i].z); bp[3] = f2tf32(bv[i].w);
        }
        __syncthreads();

        #pragma unroll
        for (int kk = 0; kk < 32; kk += 8) {
            uint32_t a[2][4];
            #pragma unroll
            for (int mt = 0; mt < 2; mt++) {
                const uint32_t* base = As + (wm + mt * 16 + g) * SPITCH + kk + t4;
                a[mt][0] = base[0];
                a[mt][1] = base[8 * SPITCH];
                a[mt][2] = base[4];
                a[mt][3] = base[8 * SPITCH + 4];
            }
            #pragma unroll
            for (int nt = 0; nt < 8; nt++) {
                const uint32_t* bb = Bs + (wn + nt * 8 + g) * SPITCH + kk + t4;
                uint32_t b0 = bb[0];
                uint32_t b1 = bb[4];
                #pragma unroll
                for (int mt = 0; mt < 2; mt++) {
                    MMA_TF32(c[mt][nt], a[mt][0], a[mt][1], a[mt][2], a[mt][3], b0, b1);
                }
            }
        }
    }

    #pragma unroll
    for (int mt = 0; mt < 2; mt++) {
        #pragma unroll
        for (int nt = 0; nt < 8; nt++) {
            const int col = bn + wn + nt * 8 + 2 * t4;
            float bx = 0.f, by = 0.f;
            if (BIAS) { bx = bias[col]; by = bias[col + 1]; }
            const int r0 = bm + wm + mt * 16 + g;
            float2 v0 = make_float2(c[mt][nt][0] + bx, c[mt][nt][1] + by);
            float2 v1 = make_float2(c[mt][nt][2] + bx, c[mt][nt][3] + by);
            *(float2*)(C + (size_t)r0 * 1024 + col)       = v0;
            *(float2*)(C + (size_t)(r0 + 8) * 1024 + col) = v1;
        }
    }
}

// ---------------------------------------------------------------------------
// Tensor-core flash attention (tf32 mma.sync).
// CTA = one (b, h, 64-query tile); 4 warps x 16 query rows; KV tiles of 64.
// Smem word layout: Ks[64][68] @0, Vs[64][72] @4352, QP[64][68] @8960,
//                   pms[64] @13312.  Total 13376 words = 53504 B.
// ---------------------------------------------------------------------------
#define KP 68
#define VP 72
#define ATT_SMEM_WORDS (64*KP + 64*VP + 64*KP + 64)

__global__ __launch_bounds__(128) void attn_mma(
    const float* __restrict__ Q, const float* __restrict__ K,
    const float* __restrict__ V, const int* __restrict__ pmask,
    const int* __restrict__ fmask, float* __restrict__ O)
{
    extern __shared__ uint32_t dsm[];
    uint32_t* Ks  = dsm;                    // [64][KP]
    uint32_t* Vs  = dsm + 64*KP;            // [64][VP]  (row-major V, tf32)
    uint32_t* QP  = dsm + 64*KP + 64*VP;    // [64][KP]  Q staging, then P
    int*      pms = (int*)(dsm + 64*KP + 64*VP + 64*KP);

    const int b  = blockIdx.z;
    const int h  = blockIdx.y;
    const int q0 = SEQ - 64 - blockIdx.x * 64;   // heavy CTAs first
    const int tid  = threadIdx.x;
    const int w    = tid >> 5;
    const int lane = tid & 31;
    const int g    = lane >> 2;
    const int t4   = lane & 3;

    const bool causal = (*fmask != 0);
    const int* pm = pmask + (size_t)b * SEQ;

    // ---- stage Q (scaled, tf32) ----
    {
        const float scale = 0.125f;
        #pragma unroll
        for (int i = tid; i < 64 * 16; i += 128) {
            int row = i >> 4;
            int c4  = i & 15;
            float4 t = *(const float4*)(Q + (size_t)(b*SEQ + q0 + row) * INNER + h*HD + c4*4);
            uint32_t* p = QP + row * KP + c4 * 4;
            p[0] = f2tf32(t.x * scale); p[1] = f2tf32(t.y * scale);
            p[2] = f2tf32(t.z * scale); p[3] = f2tf32(t.w * scale);
        }
    }
    __syncthreads();

    // ---- Q fragments (A operand), register resident ----
    uint32_t qf[8][4];
    #pragma unroll
    for (int kt = 0; kt < 8; kt++) {
        const uint32_t* base = QP + (w*16 + g) * KP + kt*8 + t4;
        qf[kt][0] = base[0];
        qf[kt][1] = base[8*KP];
        qf[kt][2] = base[4];
        qf[kt][3] = base[8*KP + 4];
    }
    __syncthreads();   // QP now free for P

    float o[8][4];
    #pragma unroll
    for (int nt = 0; nt < 8; nt++)
        #pragma unroll
        for (int i = 0; i < 4; i++) o[nt][i] = 0.f;

    float m0 = -INFINITY, m1 = -INFINITY, l0 = 0.f, l1 = 0.f;
    const int r0 = q0 + w*16 + g;        // global query row (and r0+8)

    const int ntiles = causal ? (q0/64 + 1) : (SEQ/64);

    for (int tile = 0; tile < ntiles; tile++) {
        const int j0 = tile * 64;
        __syncthreads();   // previous tile's smem reads complete

        // ---- load K and V tiles (tf32), plus pmask slice ----
        #pragma unroll
        for (int i = tid; i < 64 * 16; i += 128) {
            int row = i >> 4;
            int c4  = i & 15;
            const size_t goff = (size_t)(b*SEQ + j0 + row) * INNER + h*HD + c4*4;
            float4 kv = *(const float4*)(K + goff);
            float4 vv = *(const float4*)(V + goff);
            uint32_t* kp = Ks + row * KP + c4 * 4;
            uint32_t* vp = Vs + row * VP + c4 * 4;
            kp[0] = f2tf32(kv.x); kp[1] = f2tf32(kv.y);
            kp[2] = f2tf32(kv.z); kp[3] = f2tf32(kv.w);
            vp[0] = f2tf32(vv.x); vp[1] = f2tf32(vv.y);
            vp[2] = f2tf32(vv.z); vp[3] = f2tf32(vv.w);
        }
        if (tid < 64) pms[tid] = pm[j0 + tid];
        __syncthreads();

        // ---- S = Q @ K^T ----
        float s[8][4];
        #pragma unroll
        for (int nt = 0; nt < 8; nt++)
            #pragma unroll
            for (int i = 0; i < 4; i++) s[nt][i] = 0.f;

        #pragma unroll
        for (int kt = 0; kt < 8; kt++) {
            #pragma unroll
            for (int nt = 0; nt < 8; nt++) {
                const uint32_t* bb = Ks + (nt*8 + g) * KP + kt*8 + t4;
                uint32_t b0 = bb[0];
                uint32_t b1 = bb[4];
                MMA_TF32(s[nt], qf[kt][0], qf[kt][1], qf[kt][2], qf[kt][3], b0, b1);
            }
        }

        // ---- mask ----
        const bool diag = causal && (tile == ntiles - 1);
        #pragma unroll
        for (int nt = 0; nt < 8; nt++) {
            const int c0 = nt*8 + 2*t4;
            const int c1 = c0 + 1;
            const bool p0 = (pms[c0] != 0);
            const bool p1 = (pms[c1] != 0);
            if (!p0 || (diag && j0 + c0 > r0))     s[nt][0] = -INFINITY;
            if (!p1 || (diag && j0 + c1 > r0))     s[nt][1] = -INFINITY;
            if (!p0 || (diag && j0 + c0 > r0 + 8)) s[nt][2] = -INFINITY;
            if (!p1 || (diag && j0 + c1 > r0 + 8)) s[nt][3] = -INFINITY;
        }

        // ---- online softmax ----
        float t0 = -INFINITY, t1 = -INFINITY;
        #pragma unroll
        for (int nt = 0; nt < 8; nt++) {
            t0 = fmaxf(t0, fmaxf(s[nt][0], s[nt][1]));
            t1 = fmaxf(t1, fmaxf(s[nt][2], s[nt][3]));
        }
        t0 = fmaxf(t0, __shfl_xor_sync(0xFFFFFFFFu, t0, 1));
        t0 = fmaxf(t0, __shfl_xor_sync(0xFFFFFFFFu, t0, 2));
        t1 = fmaxf(t1, __shfl_xor_sync(0xFFFFFFFFu, t1, 1));
        t1 = fmaxf(t1, __shfl_xor_sync(0xFFFFFFFFu, t1, 2));

        const float mn0 = fmaxf(m0, t0);
        const float mn1 = fmaxf(m1, t1);
        const float corr0 = __expf(m0 - mn0);
        const float corr1 = __expf(m1 - mn1);
        m0 = mn0; m1 = mn1;

        float sum0 = 0.f, sum1 = 0.f;
        #pragma unroll
        for (int nt = 0; nt < 8; nt++) {
            s[nt][0] = __expf(s[nt][0] - mn0); sum0 += s[nt][0];
            s[nt][1] = __expf(s[nt][1] - mn0); sum0 += s[nt][1];
            s[nt][2] = __expf(s[nt][2] - mn1); sum1 += s[nt][2];
            s[nt][3] = __expf(s[nt][3] - mn1); sum1 += s[nt][3];
        }
        sum0 += __shfl_xor_sync(0xFFFFFFFFu, sum0, 1);
        sum0 += __shfl_xor_sync(0xFFFFFFFFu, sum0, 2);
        sum1 += __shfl_xor_sync(0xFFFFFFFFu, sum1, 1);
        sum1 += __shfl_xor_sync(0xFFFFFFFFu, sum1, 2);
        l0 = l0 * corr0 + sum0;
        l1 = l1 * corr1 + sum1;

        // ---- P -> warp-private smem (tf32), reload as A fragments ----
        uint32_t* Ps = QP + w * 16 * KP;
        #pragma unroll
        for (int nt = 0; nt < 8; nt++) {
            const int c0 = nt*8 + 2*t4;
            Ps[g*KP + c0]           = f2tf32(s[nt][0]);
            Ps[g*KP + c0 + 1]       = f2tf32(s[nt][1]);
            Ps[(g+8)*KP + c0]       = f2tf32(s[nt][2]);
            Ps[(g+8)*KP + c0 + 1]   = f2tf32(s[nt][3]);
        }
        __syncwarp();

        // rescale O
        #pragma unroll
        for (int nt = 0; nt < 8; nt++) {
            o[nt][0] *= corr0; o[nt][1] *= corr0;
            o[nt][2] *= corr1; o[nt][3] *= corr1;
        }

        // ---- O += P @ V ----
        #pragma unroll
        for (int kt = 0; kt < 8; kt++) {
            uint32_t a0 = Ps[g*KP + kt*8 + t4];
            uint32_t a1 = Ps[(g+8)*KP + kt*8 + t4];
            uint32_t a2 = Ps[g*KP + kt*8 + t4 + 4];
            uint32_t a3 = Ps[(g+8)*KP + kt*8 + t4 + 4];
            #pragma unroll
            for (int nt = 0; nt < 8; nt++) {
                uint32_t b0 = Vs[(kt*8 + t4)     * VP + nt*8 + g];
                uint32_t b1 = Vs[(kt*8 + t4 + 4) * VP + nt*8 + g];
                MMA_TF32(o[nt], a0, a1, a2, a3, b0, b1);
            }
        }
    }

    // ---- epilogue ----
    const float inv0 = 1.f / l0;
    const float inv1 = 1.f / l1;
    float* op0 = O + (size_t)(b*SEQ + r0)     * INNER + h*HD;
    float* op1 = O + (size_t)(b*SEQ + r0 + 8) * INNER + h*HD;
    #pragma unroll
    for (int nt = 0; nt < 8; nt++) {
        const int col = nt*8 + 2*t4;
        *(float2*)(op0 + col) = make_float2(o[nt][0]*inv0, o[nt][1]*inv0);
        *(float2*)(op1 + col) = make_float2(o[nt][2]*inv1, o[nt][3]*inv1);
    }
}

// ---------------------------------------------------------------------------
extern "C" void kernel_launch(void* const* d_in, const int* in_sizes, int n_in,
                              void* d_out, int out_size)
{
    const float* query = (const float*)d_in[0];
    const float* key   = (const float*)d_in[1];
    const float* value = (const float*)d_in[2];
    const int*   pmask = (const int*)d_in[3];
    const int*   fmask = (const int*)d_in[4];
    const float* Wq = (const float*)d_in[5];
    const float* Wk = (const float*)d_in[6];
    const float* Wv = (const float*)d_in[7];
    const float* Wo = (const float*)d_in[8];
    const float* bo = (const float*)d_in[9];
    float* out = (float*)d_out;

    float *gq, *gk, *gv, *gatt;
    cudaGetSymbolAddress((void**)&gq,   g_q);
    cudaGetSymbolAddress((void**)&gk,   g_k);
    cudaGetSymbolAddress((void**)&gv,   g_v);
    cudaGetSymbolAddress((void**)&gatt, g_att);

    const int SMEM_BYTES = 2 * 128 * SPITCH * 4;   // 36864
    cudaFuncSetAttribute(gemm_tf32<false>,
                         cudaFuncAttributeMaxDynamicSharedMemorySize, SMEM_BYTES);
    cudaFuncSetAttribute(gemm_tf32<true>,
                         cudaFuncAttributeMaxDynamicSharedMemorySize, SMEM_BYTES);

    const int ATT_BYTES = ATT_SMEM_WORDS * 4;      // 53504
    cudaFuncSetAttribute(attn_mma,
                         cudaFuncAttributeMaxDynamicSharedMemorySize, ATT_BYTES);

    dim3 ggrid(INNER/128, MROWS/128);   // (8, 32)
    gemm_tf32<false><<<ggrid, 256, SMEM_BYTES>>>(query, Wq, nullptr, gq);
    gemm_tf32<false><<<ggrid, 256, SMEM_BYTES>>>(key,   Wk, nullptr, gk);
    gemm_tf32<false><<<ggrid, 256, SMEM_BYTES>>>(value, Wv, nullptr, gv);

    dim3 agrid(SEQ/64, NH, BATCH);      // (32, 16, 2)
    attn_mma<<<agrid, 128, ATT_BYTES>>>(gq, gk, gv, pmask, fmask, gatt);

    dim3 ogrid(EMB/128, MROWS/128);     // (8, 32)
    gemm_tf32<true><<<ogrid, 256, SMEM_BYTES>>>(gatt, Wo, bo, out);
}

// round 12
// speedup vs baseline: 4.0383x; 1.1208x over previous
#include <cuda_runtime.h>
#include <cstdint>
#include <math.h>

#define EMB   1024
#define NH    16
#define HD    64
#define INNER 1024
#define BATCH 2
#define SEQ   2048
#define MROWS (BATCH*SEQ)   // 4096

// Scratch (allocation-free rule: device globals)
__device__ float g_q[(size_t)MROWS*INNER];
__device__ float g_k[(size_t)MROWS*INNER];
__device__ float g_v[(size_t)MROWS*INNER];
__device__ float g_att[(size_t)MROWS*INNER];

__device__ __forceinline__ uint32_t f2tf32(float x) {
    uint32_t r;
    asm("cvt.rna.tf32.f32 %0, %1;" : "=r"(r) : "f"(x));
    return r;
}

#define MMA_TF32(c, a0,a1,a2,a3, b0,b1)                                        \
    asm volatile(                                                              \
        "mma.sync.aligned.m16n8k8.row.col.f32.tf32.tf32.f32 "                  \
        "{%0,%1,%2,%3}, {%4,%5,%6,%7}, {%8,%9}, {%0,%1,%2,%3};"                \
        : "+f"((c)[0]), "+f"((c)[1]), "+f"((c)[2]), "+f"((c)[3])               \
        : "r"(a0), "r"(a1), "r"(a2), "r"(a3), "r"(b0), "r"(b1))

// ---------------------------------------------------------------------------
// TF32 mma.sync GEMM, fragment-major smem + double buffer.
// C[m][n] = sum_k A[m][k]*W[n][k] (+bias[n]).  CTA 128x128, K-chunk 32.
// 8 warps (4m x 2n), warp tile 32x64.
//
// A fragment blocks: (mg, ks) mg=row/16, ks=kcol/8; 128+4 pad words each.
//   lane(g,t4) words [a0,a1,a2,a3] contiguous at (g*4+t4)*4 -> one LDS.128.
// B fragment blocks: (ng, ks) ng=nrow/8; 64+2 pad words each.
//   lane(g,t4) words [b0,b1] contiguous at (g*4+t4)*2 -> one LDS.64.
// ---------------------------------------------------------------------------
#define APITCH 132
#define BPITCH 66
#define ABUF (32*APITCH)                 // 4224 words
#define BBUF (64*BPITCH)                 // 4224 words
#define GEMM_SMEM_WORDS (2*ABUF + 2*BBUF)
#define GEMM_SMEM_BYTES (GEMM_SMEM_WORDS*4)   // 67584

template<bool BIAS>
__device__ __forceinline__ void gemm_core(
    const float* __restrict__ A, const float* __restrict__ W,
    const float* __restrict__ bias, float* __restrict__ C,
    const int bm, const int bn)
{
    extern __shared__ uint32_t sm[];
    uint32_t* const SA0 = sm;
    uint32_t* const SA1 = sm + ABUF;
    uint32_t* const SB0 = sm + 2*ABUF;
    uint32_t* const SB1 = sm + 2*ABUF + BBUF;

    const int tid  = threadIdx.x;
    const int wid  = tid >> 5;
    const int lane = tid & 31;
    const int g    = lane >> 2;
    const int t4   = lane & 3;
    const int mg0  = (wid & 3) * 2;      // A 16-row block base
    const int ng0  = (wid >> 2) * 8;     // B 8-row block base
    const int K    = 1024;

    const int lrow  = tid >> 3;          // 0..31
    const int lc4   = tid & 7;           // float4 index in 32-col chunk
    const int ks_st = lc4 >> 1;
    const int wA    = (lc4 & 1) * 2;
    const int wB    = lc4 & 1;

    float c[2][8][4];
    #pragma unroll
    for (int mt = 0; mt < 2; mt++)
        #pragma unroll
        for (int nt = 0; nt < 8; nt++)
            #pragma unroll
            for (int i = 0; i < 4; i++) c[mt][nt][i] = 0.f;

    float4 av[4], bv[4];

    // ---- prologue: chunk 0 -> buf 0 ----
    #pragma unroll
    for (int i = 0; i < 4; i++) {
        int row = lrow + i * 32;
        av[i] = *(const float4*)(A + (size_t)(bm + row) * K + lc4 * 4);
        bv[i] = *(const float4*)(W + (size_t)(bn + row) * K + lc4 * 4);
    }
    #pragma unroll
    for (int i = 0; i < 4; i++) {
        int row = lrow + i * 32;
        int mg = row >> 4, lr = row & 15, hw = lr >> 3, ga = lr & 7;
        uint32_t ab = (mg * 4 + ks_st) * APITCH + ga * 16 + wA + hw;
        SA0[ab+0]  = f2tf32(av[i].x); SA0[ab+4]  = f2tf32(av[i].y);
        SA0[ab+8]  = f2tf32(av[i].z); SA0[ab+12] = f2tf32(av[i].w);
        int ng = row >> 3, gb = row & 7;
        uint32_t bb = (ng * 4 + ks_st) * BPITCH + gb * 8 + wB;
        SB0[bb+0] = f2tf32(bv[i].x); SB0[bb+2] = f2tf32(bv[i].y);
        SB0[bb+4] = f2tf32(bv[i].z); SB0[bb+6] = f2tf32(bv[i].w);
    }
    __syncthreads();

    for (int ch = 0; ch < 32; ch++) {
        const int p = ch & 1;
        // stage next chunk's gmem loads (hidden behind mma below)
        if (ch < 31) {
            const int k0 = (ch + 1) * 32;
            #pragma unroll
            for (int i = 0; i < 4; i++) {
                int row = lrow + i * 32;
                av[i] = *(const float4*)(A + (size_t)(bm + row) * K + k0 + lc4 * 4);
                bv[i] = *(const float4*)(W + (size_t)(bn + row) * K + k0 + lc4 * 4);
            }
        }

        const uint32_t* sa = p ? SA1 : SA0;
        const uint32_t* sb = p ? SB1 : SB0;
        #pragma unroll
        for (int ks = 0; ks < 4; ks++) {
            uint4 a0 = *(const uint4*)&sa[((mg0    ) * 4 + ks) * APITCH + (g*4 + t4) * 4];
            uint4 a1 = *(const uint4*)&sa[((mg0 + 1) * 4 + ks) * APITCH + (g*4 + t4) * 4];
            #pragma unroll
            for (int nt = 0; nt < 8; nt++) {
                uint2 b = *(const uint2*)&sb[((ng0 + nt) * 4 + ks) * BPITCH + (g*4 + t4) * 2];
                MMA_TF32(c[0][nt], a0.x, a0.y, a0.z, a0.w, b.x, b.y);
                MMA_TF32(c[1][nt], a1.x, a1.y, a1.z, a1.w, b.x, b.y);
            }
        }

        if (ch < 31) {
            uint32_t* da = p ? SA0 : SA1;
            uint32_t* db = p ? SB0 : SB1;
            #pragma unroll
            for (int i = 0; i < 4; i++) {
                int row = lrow + i * 32;
                int mg = row >> 4, lr = row & 15, hw = lr >> 3, ga = lr & 7;
                uint32_t ab = (mg * 4 + ks_st) * APITCH + ga * 16 + wA + hw;
                da[ab+0]  = f2tf32(av[i].x); da[ab+4]  = f2tf32(av[i].y);
                da[ab+8]  = f2tf32(av[i].z); da[ab+12] = f2tf32(av[i].w);
                int ng = row >> 3, gb = row & 7;
                uint32_t bb = (ng * 4 + ks_st) * BPITCH + gb * 8 + wB;
                db[bb+0] = f2tf32(bv[i].x); db[bb+2] = f2tf32(bv[i].y);
                db[bb+4] = f2tf32(bv[i].z); db[bb+6] = f2tf32(bv[i].w);
            }
            __syncthreads();
        }
    }

    // ---- epilogue ----
    const int wm = (wid & 3) * 32;
    const int wn = (wid >> 2) * 64;
    #pragma unroll
    for (int mt = 0; mt < 2; mt++) {
        #pragma unroll
        for (int nt = 0; nt < 8; nt++) {
            const int col = bn + wn + nt * 8 + 2 * t4;
            float bx = 0.f, by = 0.f;
            if (BIAS) { bx = bias[col]; by = bias[col + 1]; }
            const int r0 = bm + wm + mt * 16 + g;
            float2 v0 = make_float2(c[mt][nt][0] + bx, c[mt][nt][1] + by);
            float2 v1 = make_float2(c[mt][nt][2] + bx, c[mt][nt][3] + by);
            *(float2*)(C + (size_t)r0 * 1024 + col)       = v0;
            *(float2*)(C + (size_t)(r0 + 8) * 1024 + col) = v1;
        }
    }
}

__global__ __launch_bounds__(256) void gemm_qkv(
    const float* __restrict__ q, const float* __restrict__ k,
    const float* __restrict__ v,
    const float* __restrict__ Wq, const float* __restrict__ Wk,
    const float* __restrict__ Wv,
    float* __restrict__ oq, float* __restrict__ ok, float* __restrict__ ov)
{
    const float* A; const float* W; float* C;
    if (blockIdx.z == 0)      { A = q; W = Wq; C = oq; }
    else if (blockIdx.z == 1) { A = k; W = Wk; C = ok; }
    else                      { A = v; W = Wv; C = ov; }
    gemm_core<false>(A, W, nullptr, C, blockIdx.y * 128, blockIdx.x * 128);
}

__global__ __launch_bounds__(256) void gemm_out(
    const float* __restrict__ A, const float* __restrict__ W,
    const float* __restrict__ bias, float* __restrict__ C)
{
    gemm_core<true>(A, W, bias, C, blockIdx.y * 128, blockIdx.x * 128);
}

// ---------------------------------------------------------------------------
// Tensor-core flash attention (unchanged from R11 passing version).
// ---------------------------------------------------------------------------
#define KP 68
#define VP 72
#define ATT_SMEM_WORDS (64*KP + 64*VP + 64*KP + 64)

__global__ __launch_bounds__(128) void attn_mma(
    const float* __restrict__ Q, const float* __restrict__ K,
    const float* __restrict__ V, const int* __restrict__ pmask,
    const int* __restrict__ fmask, float* __restrict__ O)
{
    extern __shared__ uint32_t dsm[];
    uint32_t* Ks  = dsm;                    // [64][KP]
    uint32_t* Vs  = dsm + 64*KP;            // [64][VP]
    uint32_t* QP  = dsm + 64*KP + 64*VP;    // [64][KP]
    int*      pms = (int*)(dsm + 64*KP + 64*VP + 64*KP);

    const int b  = blockIdx.z;
    const int h  = blockIdx.y;
    const int q0 = SEQ - 64 - blockIdx.x * 64;
    const int tid  = threadIdx.x;
    const int w    = tid >> 5;
    const int lane = tid & 31;
    const int g    = lane >> 2;
    const int t4   = lane & 3;

    const bool causal = (*fmask != 0);
    const int* pm = pmask + (size_t)b * SEQ;

    {
        const float scale = 0.125f;
        #pragma unroll
        for (int i = tid; i < 64 * 16; i += 128) {
            int row = i >> 4;
            int c4  = i & 15;
            float4 t = *(const float4*)(Q + (size_t)(b*SEQ + q0 + row) * INNER + h*HD + c4*4);
            uint32_t* p = QP + row * KP + c4 * 4;
            p[0] = f2tf32(t.x * scale); p[1] = f2tf32(t.y * scale);
            p[2] = f2tf32(t.z * scale); p[3] = f2tf32(t.w * scale);
        }
    }
    __syncthreads();

    uint32_t qf[8][4];
    #pragma unroll
    for (int kt = 0; kt < 8; kt++) {
        const uint32_t* base = QP + (w*16 + g) * KP + kt*8 + t4;
        qf[kt][0] = base[0];
        qf[kt][1] = base[8*KP];
        qf[kt][2] = base[4];
        qf[kt][3] = base[8*KP + 4];
    }
    __syncthreads();

    float o[8][4];
    #pragma unroll
    for (int nt = 0; nt < 8; nt++)
        #pragma unroll
        for (int i = 0; i < 4; i++) o[nt][i] = 0.f;

    float m0 = -INFINITY, m1 = -INFINITY, l0 = 0.f, l1 = 0.f;
    const int r0 = q0 + w*16 + g;

    const int ntiles = causal ? (q0/64 + 1) : (SEQ/64);

    for (int tile = 0; tile < ntiles; tile++) {
        const int j0 = tile * 64;
        __syncthreads();

        #pragma unroll
        for (int i = tid; i < 64 * 16; i += 128) {
            int row = i >> 4;
            int c4  = i & 15;
            const size_t goff = (size_t)(b*SEQ + j0 + row) * INNER + h*HD + c4*4;
            float4 kv = *(const float4*)(K + goff);
            float4 vv = *(const float4*)(V + goff);
            uint32_t* kp = Ks + row * KP + c4 * 4;
            uint32_t* vp = Vs + row * VP + c4 * 4;
            kp[0] = f2tf32(kv.x); kp[1] = f2tf32(kv.y);
            kp[2] = f2tf32(kv.z); kp[3] = f2tf32(kv.w);
            vp[0] = f2tf32(vv.x); vp[1] = f2tf32(vv.y);
            vp[2] = f2tf32(vv.z); vp[3] = f2tf32(vv.w);
        }
        if (tid < 64) pms[tid] = pm[j0 + tid];
        __syncthreads();

        float s[8][4];
        #pragma unroll
        for (int nt = 0; nt < 8; nt++)
            #pragma unroll
            for (int i = 0; i < 4; i++) s[nt][i] = 0.f;

        #pragma unroll
        for (int kt = 0; kt < 8; kt++) {
            #pragma unroll
            for (int nt = 0; nt < 8; nt++) {
                const uint32_t* bb = Ks + (nt*8 + g) * KP + kt*8 + t4;
                uint32_t b0 = bb[0];
                uint32_t b1 = bb[4];
                MMA_TF32(s[nt], qf[kt][0], qf[kt][1], qf[kt][2], qf[kt][3], b0, b1);
            }
        }

        const bool diag = causal && (tile == ntiles - 1);
        #pragma unroll
        for (int nt = 0; nt < 8; nt++) {
            const int c0 = nt*8 + 2*t4;
            const int c1 = c0 + 1;
            const bool p0 = (pms[c0] != 0);
            const bool p1 = (pms[c1] != 0);
            if (!p0 || (diag && j0 + c0 > r0))     s[nt][0] = -INFINITY;
            if (!p1 || (diag && j0 + c1 > r0))     s[nt][1] = -INFINITY;
            if (!p0 || (diag && j0 + c0 > r0 + 8)) s[nt][2] = -INFINITY;
            if (!p1 || (diag && j0 + c1 > r0 + 8)) s[nt][3] = -INFINITY;
        }

        float t0 = -INFINITY, t1 = -INFINITY;
        #pragma unroll
        for (int nt = 0; nt < 8; nt++) {
            t0 = fmaxf(t0, fmaxf(s[nt][0], s[nt][1]));
            t1 = fmaxf(t1, fmaxf(s[nt][2], s[nt][3]));
        }
        t0 = fmaxf(t0, __shfl_xor_sync(0xFFFFFFFFu, t0, 1));
        t0 = fmaxf(t0, __shfl_xor_sync(0xFFFFFFFFu, t0, 2));
        t1 = fmaxf(t1, __shfl_xor_sync(0xFFFFFFFFu, t1, 1));
        t1 = fmaxf(t1, __shfl_xor_sync(0xFFFFFFFFu, t1, 2));

        const float mn0 = fmaxf(m0, t0);
        const float mn1 = fmaxf(m1, t1);
        const float corr0 = __expf(m0 - mn0);
        const float corr1 = __expf(m1 - mn1);
        m0 = mn0; m1 = mn1;

        float sum0 = 0.f, sum1 = 0.f;
        #pragma unroll
        for (int nt = 0; nt < 8; nt++) {
            s[nt][0] = __expf(s[nt][0] - mn0); sum0 += s[nt][0];
            s[nt][1] = __expf(s[nt][1] - mn0); sum0 += s[nt][1];
            s[nt][2] = __expf(s[nt][2] - mn1); sum1 += s[nt][2];
            s[nt][3] = __expf(s[nt][3] - mn1); sum1 += s[nt][3];
        }
        sum0 += __shfl_xor_sync(0xFFFFFFFFu, sum0, 1);
        sum0 += __shfl_xor_sync(0xFFFFFFFFu, sum0, 2);
        sum1 += __shfl_xor_sync(0xFFFFFFFFu, sum1, 1);
        sum1 += __shfl_xor_sync(0xFFFFFFFFu, sum1, 2);
        l0 = l0 * corr0 + sum0;
        l1 = l1 * corr1 + sum1;

        uint32_t* Ps = QP + w * 16 * KP;
        #pragma unroll
        for (int nt = 0; nt < 8; nt++) {
            const int c0 = nt*8 + 2*t4;
            Ps[g*KP + c0]           = f2tf32(s[nt][0]);
            Ps[g*KP + c0 + 1]       = f2tf32(s[nt][1]);
            Ps[(g+8)*KP + c0]       = f2tf32(s[nt][2]);
            Ps[(g+8)*KP + c0 + 1]   = f2tf32(s[nt][3]);
        }
        __syncwarp();

        #pragma unroll
        for (int nt = 0; nt < 8; nt++) {
            o[nt][0] *= corr0; o[nt][1] *= corr0;
            o[nt][2] *= corr1; o[nt][3] *= corr1;
        }

        #pragma unroll
        for (int kt = 0; kt < 8; kt++) {
            uint32_t a0 = Ps[g*KP + kt*8 + t4];
            uint32_t a1 = Ps[(g+8)*KP + kt*8 + t4];
            uint32_t a2 = Ps[g*KP + kt*8 + t4 + 4];
            uint32_t a3 = Ps[(g+8)*KP + kt*8 + t4 + 4];
            #pragma unroll
            for (int nt = 0; nt < 8; nt++) {
                uint32_t b0 = Vs[(kt*8 + t4)     * VP + nt*8 + g];
                uint32_t b1 = Vs[(kt*8 + t4 + 4) * VP + nt*8 + g];
                MMA_TF32(o[nt], a0, a1, a2, a3, b0, b1);
            }
        }
    }

    const float inv0 = 1.f / l0;
    const float inv1 = 1.f / l1;
    float* op0 = O + (size_t)(b*SEQ + r0)     * INNER + h*HD;
    float* op1 = O + (size_t)(b*SEQ + r0 + 8) * INNER + h*HD;
    #pragma unroll
    for (int nt = 0; nt < 8; nt++) {
        const int col = nt*8 + 2*t4;
        *(float2*)(op0 + col) = make_float2(o[nt][0]*inv0, o[nt][1]*inv0);
        *(float2*)(op1 + col) = make_float2(o[nt][2]*inv1, o[nt][3]*inv1);
    }
}

// ---------------------------------------------------------------------------
extern "C" void kernel_launch(void* const* d_in, const int* in_sizes, int n_in,
                              void* d_out, int out_size)
{
    const float* query = (const float*)d_in[0];
    const float* key   = (const float*)d_in[1];
    const float* value = (const float*)d_in[2];
    const int*   pmask = (const int*)d_in[3];
    const int*   fmask = (const int*)d_in[4];
    const float* Wq = (const float*)d_in[5];
    const float* Wk = (const float*)d_in[6];
    const float* Wv = (const float*)d_in[7];
    const float* Wo = (const float*)d_in[8];
    const float* bo = (const float*)d_in[9];
    float* out = (float*)d_out;

    float *gq, *gk, *gv, *gatt;
    cudaGetSymbolAddress((void**)&gq,   g_q);
    cudaGetSymbolAddress((void**)&gk,   g_k);
    cudaGetSymbolAddress((void**)&gv,   g_v);
    cudaGetSymbolAddress((void**)&gatt, g_att);

    cudaFuncSetAttribute(gemm_qkv,
                         cudaFuncAttributeMaxDynamicSharedMemorySize, GEMM_SMEM_BYTES);
    cudaFuncSetAttribute(gemm_out,
                         cudaFuncAttributeMaxDynamicSharedMemorySize, GEMM_SMEM_BYTES);

    const int ATT_BYTES = ATT_SMEM_WORDS * 4;      // 53504
    cudaFuncSetAttribute(attn_mma,
                         cudaFuncAttributeMaxDynamicSharedMemorySize, ATT_BYTES);

    dim3 qkvgrid(INNER/128, MROWS/128, 3);  // (8, 32, 3)
    gemm_qkv<<<qkvgrid, 256, GEMM_SMEM_BYTES>>>(query, key, value,
                                                Wq, Wk, Wv, gq, gk, gv);

    dim3 agrid(SEQ/64, NH, BATCH);          // (32, 16, 2)
    attn_mma<<<agrid, 128, ATT_BYTES>>>(gq, gk, gv, pmask, fmask, gatt);

    dim3 ogrid(EMB/128, MROWS/128);         // (8, 32)
    gemm_out<<<ogrid, 256, GEMM_SMEM_BYTES>>>(gatt, Wo, bo, out);
}